// round 8
// baseline (speedup 1.0000x reference)
#include <cuda_runtime.h>
#include <math.h>

// PDELayer: 8192 x (48x48) grids, 100 explicit diffusion steps.
// One CTA per grid, 64 threads (16 col-tiles x 4 row-tiles), each thread owns a
// 3-col x 12-row register tile stored as 6 row-pair f32x2 packs per column.
// SMEM is COLUMN-MAJOR so vertical neighbors are contiguous: perimeter columns
// exchange as aligned LDS.64/STS.64 packs; horizontal neighbor packs need no
// repacking. All stencil math uses packed fma.rn.f32x2 / add.rn.f32x2 (FFMA2),
// doubling fp32 throughput vs scalar FFMA.
//
// Column stride 54: 64-bit pair-bank step across tx = 81 = 1 (mod 16) -> all
// column pack loads/stores are bank-conflict-free. Interior rows start at
// physical row 2 (even) so row-pair packs are 8B aligned.
// Reflect halo is time-invariant (reference pads once, updates interior only).

#define NG     48
#define CS     54            // column stride in floats (column-major)
#define NCOL   50            // halo col 0, interior 1..48, halo col 49
#define SMSZ   (NCOL * CS)
#define NSTEPS 100
#define TW     3
#define TH     12
#define NPK    6             // row-pair packs per column

typedef unsigned long long ull;

__device__ __forceinline__ ull f2fma(ull a, ull b, ull c) {
    ull d; asm("fma.rn.f32x2 %0,%1,%2,%3;" : "=l"(d) : "l"(a), "l"(b), "l"(c)); return d;
}
__device__ __forceinline__ ull f2add(ull a, ull b) {
    ull d; asm("add.rn.f32x2 %0,%1,%2;" : "=l"(d) : "l"(a), "l"(b)); return d;
}
__device__ __forceinline__ ull pk(float lo, float hi) {
    ull v; asm("mov.b64 %0,{%1,%2};" : "=l"(v) : "f"(lo), "f"(hi)); return v;
}
__device__ __forceinline__ void unpk(ull v, float& lo, float& hi) {
    asm("mov.b64 {%0,%1},%2;" : "=f"(lo), "=f"(hi) : "l"(v));
}

// smem index: padded coords (row_p, col_p) in 0..49; physical row = row_p+1
#define IDX(col_p, row_p) ((col_p) * CS + (row_p) + 1)

__device__ __forceinline__ void step_tile(
    const float* __restrict__ cur, float* __restrict__ nxt,
    ull P[TW][NPK], const ull A2[NPK], const ull B2[TW], const ull m2,
    int C0, int R0)   // C0: padded col of tile col 0; R0: PHYSICAL first row (even)
{
    ull N0[NPK], N1[NPK], N2[NPK];
#pragma unroll
    for (int c = 0; c < TW; c++) {
        ull* N = (c == 0) ? N0 : (c == 1) ? N1 : N2;
        const float* colT = &cur[(C0 + c) * CS];
        float prevHi = colT[R0 - 1];               // top halo/neighbor scalar
        float botLo  = colT[R0 + TH];              // bottom scalar
#pragma unroll
        for (int k = 0; k < NPK; k++) {
            float loP, hiP;
            unpk(P[c][k], loP, hiP);
            float nextLo;
            if (k < NPK - 1) { float t0, t1; unpk(P[c][k + 1], t0, t1); nextLo = t0; }
            else             { nextLo = botLo; }

            ull U = pk(prevHi, loP);               // rows (r-1, r) for pair (r, r+1)
            ull D = pk(hiP, nextLo);               // rows (r+1, r+2)
            ull t = f2add(U, D);                   // up + dn
            ull sx = f2fma(m2, P[c][k], t);        // up+dn-2u

            ull sl = (c == 0) ? *(const ull*)&cur[(C0 - 1) * CS + R0 + 2 * k] : P[c - 1][k];
            ull sr = (c == TW - 1) ? *(const ull*)&cur[(C0 + TW) * CS + R0 + 2 * k] : P[c + 1][k];
            ull s  = f2add(sl, sr);
            ull sy = f2fma(m2, P[c][k], s);        // lf+rt-2u

            ull n = f2fma(A2[k], sx, P[c][k]);
            n     = f2fma(B2[c], sy, n);
            N[k] = n;
            prevHi = hiP;
        }
    }

    // perimeter stores: full left/right columns as packs, top/bot of middle col
#pragma unroll
    for (int k = 0; k < NPK; k++) {
        *(ull*)&nxt[(C0    ) * CS + R0 + 2 * k] = N0[k];
        *(ull*)&nxt[(C0 + 2) * CS + R0 + 2 * k] = N2[k];
    }
    {
        float lo, hi;
        unpk(N1[0], lo, hi);       nxt[(C0 + 1) * CS + R0]          = lo;
        unpk(N1[NPK - 1], lo, hi); nxt[(C0 + 1) * CS + R0 + TH - 1] = hi;
    }

    // commit new state
#pragma unroll
    for (int k = 0; k < NPK; k++) { P[0][k] = N0[k]; P[1][k] = N1[k]; P[2][k] = N2[k]; }

    __syncthreads();
}

__global__ __launch_bounds__(64, 10)
void pde_stencil_kernel(const float* __restrict__ u0,
                        const float* __restrict__ a1p, const float* __restrict__ a2p,
                        const float* __restrict__ a3p, const float* __restrict__ b1p,
                        const float* __restrict__ b2p, const float* __restrict__ b3p,
                        float* __restrict__ out)
{
    __shared__ __align__(16) float buf0[SMSZ];
    __shared__ __align__(16) float buf1[SMSZ];

    const int b   = blockIdx.x;
    const int tid = threadIdx.x;
    const int tx  = tid & 15;     // col-tile 0..15
    const int ty  = tid >> 4;     // row-tile 0..3

    const float* gin  = u0  + (size_t)b * (NG * NG);
    float*       gout = out + (size_t)b * (NG * NG);

    // ---- load interior into buf0 (coalesced gmem; column-major smem) ----
#pragma unroll
    for (int k = 0; k < 36; k++) {
        int c = tid + 64 * k;              // 0..2303
        int i = c / NG, j = c % NG;        // row, col
        buf0[IDX(j + 1, i + 1)] = gin[c];
    }
    __syncthreads();

    // ---- reflect halo (time-invariant) into BOTH buffers ----
    for (int h = tid; h < 196; h += 64) {
        int ii, jj;                         // padded (row, col)
        if      (h < 50)  { ii = 0;       jj = h;       }
        else if (h < 100) { ii = 49;      jj = h - 50;  }
        else if (h < 148) { ii = h - 99;  jj = 0;       }   // rows 1..48
        else              { ii = h - 147; jj = 49;      }   // rows 1..48
        int si = (ii == 0) ? 2 : (ii == 49) ? 47 : ii;
        int sj = (jj == 0) ? 2 : (jj == 49) ? 47 : jj;
        float v = buf0[IDX(sj, si)];
        buf0[IDX(jj, ii)] = v;
        buf1[IDX(jj, ii)] = v;
    }

    // ---- coefficients ----
    const float aw1 = fabsf(*a1p), aw2 = fabsf(*a2p), aw3 = fabsf(*a3p);
    const float bw1 = fabsf(*b1p), bw2 = fabsf(*b2p), bw3 = fabsf(*b3p);
    const float CA = 0.1152f;                 // 0.5*DT/DX^2
    const float CB = 0.2304f;                 // DT/DY^2
    const float TP = 6.283185307179586f;
    const float INV47 = 1.0f / 47.0f;

    const int C0 = 1 + TW * tx;      // padded col of tile's first column
    const int R0 = 2 + TH * ty;      // PHYSICAL first row (even -> 8B aligned packs)

    ull A2[NPK];
#pragma unroll
    for (int k = 0; k < NPK; k++) {
        float a[2];
#pragma unroll
        for (int p = 0; p < 2; p++) {
            float t = (float)(TH * ty + 2 * k + p) * INV47;
            a[p] = CA * (aw1 + aw2 * sinf(TP * t) + aw3 * cosf(TP * t));
        }
        A2[k] = pk(a[0], a[1]);
    }
    ull B2[TW];
#pragma unroll
    for (int c = 0; c < TW; c++) {
        float t = (float)(TW * tx + c) * INV47;
        float bv = CB * (bw1 + bw2 * cosf(TP * t) + bw3 * sinf(TP * t));
        B2[c] = pk(bv, bv);
    }
    const ull m2 = pk(-2.0f, -2.0f);

    __syncthreads();   // interior + halo visible

    // ---- own tile into packed registers ----
    ull P[TW][NPK];
#pragma unroll
    for (int c = 0; c < TW; c++)
#pragma unroll
        for (int k = 0; k < NPK; k++)
            P[c][k] = *(const ull*)&buf0[(C0 + c) * CS + R0 + 2 * k];

    // ---- 100 steps, ping-pong perimeter buffers, 1 barrier/step ----
    for (int s = 0; s < NSTEPS; s += 2) {
        step_tile(buf0, buf1, P, A2, B2, m2, C0, R0);
        step_tile(buf1, buf0, P, A2, B2, m2, C0, R0);
    }

    // ---- writeback straight from registers ----
#pragma unroll
    for (int c = 0; c < TW; c++)
#pragma unroll
        for (int k = 0; k < NPK; k++) {
            float lo, hi;
            unpk(P[c][k], lo, hi);
            int gr = TH * ty + 2 * k;
            int gc = TW * tx + c;
            gout[gr * NG + gc]        = lo;
            gout[(gr + 1) * NG + gc]  = hi;
        }
}

extern "C" void kernel_launch(void* const* d_in, const int* in_sizes, int n_in,
                              void* d_out, int out_size)
{
    const float* u0 = (const float*)d_in[0];
    const float* a1 = (const float*)d_in[1];
    const float* a2 = (const float*)d_in[2];
    const float* a3 = (const float*)d_in[3];
    const float* b1 = (const float*)d_in[4];
    const float* b2 = (const float*)d_in[5];
    const float* b3 = (const float*)d_in[6];
    float* out = (float*)d_out;

    int nb = in_sizes[0] / (NG * NG);   // 8192
    pde_stencil_kernel<<<nb, 64>>>(u0, a1, a2, a3, b1, b2, b3, out);
}

// round 10
// speedup vs baseline: 1.1751x; 1.1751x over previous
#include <cuda_runtime.h>
#include <math.h>

// PDELayer: 8192 x (48x48) grids, 100 explicit diffusion steps.
// One CTA per grid. 64 threads (16x4), each owns a 3-wide x 12-tall register tile.
// Double-buffered shared memory; only tile PERIMETER cells exchanged via SMEM.
// 5 fma-pipe ops/cell: n = cc*u + A[r]*(up+dn) + B[c]*(lf+rt), cc=1-2A-2B
// precomputed in registers (time-invariant). Final step skips stores+barrier.
// Reflect halo is time-invariant (reference pads once, updates interior only).

#define NG     48
#define PR     50      // padded rows
#define SS     52      // padded row stride (floats)
#define NSTEPS 100
#define TW     3       // tile width
#define TH     12      // tile height

template <bool STORE>
__device__ __forceinline__ void step_tile(
    const float* __restrict__ cur, float* __restrict__ nxt,
    float u[TH][TW], const float A[TH], const float B0, const float B1, const float B2,
    const float cc[TH][TW], int R0, int C0)
{
    float top0 = cur[(R0 - 1) * SS + C0 + 0];
    float top1 = cur[(R0 - 1) * SS + C0 + 1];
    float top2 = cur[(R0 - 1) * SS + C0 + 2];
    float bot0 = cur[(R0 + TH) * SS + C0 + 0];
    float bot1 = cur[(R0 + TH) * SS + C0 + 1];
    float bot2 = cur[(R0 + TH) * SS + C0 + 2];

    float pv0 = 0.f, pv1 = 0.f, pv2 = 0.f;   // old u[r-1]
#pragma unroll
    for (int r = 0; r < TH; r++) {
        float lf = cur[(R0 + r) * SS + C0 - 1];
        float rt = cur[(R0 + r) * SS + C0 + TW];

        float c0 = u[r][0], c1 = u[r][1], c2 = u[r][2];

        float up0 = (r == 0) ? top0 : pv0;
        float up1 = (r == 0) ? top1 : pv1;
        float up2 = (r == 0) ? top2 : pv2;
        float dn0 = (r == TH - 1) ? bot0 : u[r + 1][0];
        float dn1 = (r == TH - 1) ? bot1 : u[r + 1][1];
        float dn2 = (r == TH - 1) ? bot2 : u[r + 1][2];

        // 5 fma-pipe ops per cell
        float t0 = up0 + dn0;
        float s0 = lf + c1;
        float n0 = cc[r][0] * c0;
        n0 = fmaf(A[r], t0, n0);
        n0 = fmaf(B0,   s0, n0);

        float t1 = up1 + dn1;
        float s1 = c0 + c2;
        float n1 = cc[r][1] * c1;
        n1 = fmaf(A[r], t1, n1);
        n1 = fmaf(B1,   s1, n1);

        float t2 = up2 + dn2;
        float s2 = c1 + rt;
        float n2 = cc[r][2] * c2;
        n2 = fmaf(A[r], t2, n2);
        n2 = fmaf(B2,   s2, n2);

        if (STORE) {
            float* nrow = &nxt[(R0 + r) * SS + C0];
            if (r == 0 || r == TH - 1) {
                nrow[0] = n0; nrow[1] = n1; nrow[2] = n2;
            } else {
                nrow[0] = n0; nrow[2] = n2;
            }
        }

        pv0 = c0; pv1 = c1; pv2 = c2;
        u[r][0] = n0; u[r][1] = n1; u[r][2] = n2;
    }
    if (STORE) __syncthreads();
}

__global__ __launch_bounds__(64, 8)
void pde_stencil_kernel(const float* __restrict__ u0,
                        const float* __restrict__ a1p, const float* __restrict__ a2p,
                        const float* __restrict__ a3p, const float* __restrict__ b1p,
                        const float* __restrict__ b2p, const float* __restrict__ b3p,
                        float* __restrict__ out)
{
    __shared__ float buf0[PR * SS];
    __shared__ float buf1[PR * SS];

    const int b   = blockIdx.x;
    const int tid = threadIdx.x;
    const int tx  = tid & 15;     // tile col 0..15
    const int ty  = tid >> 4;     // tile row 0..3

    const float* gin  = u0  + (size_t)b * (NG * NG);
    float*       gout = out + (size_t)b * (NG * NG);

    // ---- coalesced load of interior into buf0 ----
#pragma unroll
    for (int k = 0; k < 36; k++) {
        int c = tid + 64 * k;               // 0..2303
        int i = c / NG, j = c % NG;
        buf0[(i + 1) * SS + (j + 1)] = gin[c];
    }
    __syncthreads();

    // ---- reflect halo (time-invariant) into BOTH buffers ----
    for (int h = tid; h < 196; h += 64) {
        int ii, jj;
        if      (h < 50)  { ii = 0;         jj = h;        }
        else if (h < 100) { ii = 49;        jj = h - 50;   }
        else if (h < 148) { ii = h - 99;    jj = 0;        }   // 1..48
        else              { ii = h - 147;   jj = 49;       }   // 1..48
        int si = (ii == 0) ? 2 : (ii == 49) ? 47 : ii;
        int sj = (jj == 0) ? 2 : (jj == 49) ? 47 : jj;
        float v = buf0[si * SS + sj];
        buf0[ii * SS + jj] = v;
        buf1[ii * SS + jj] = v;
    }

    // ---- per-thread coefficients ----
    const float aw1 = fabsf(*a1p), aw2 = fabsf(*a2p), aw3 = fabsf(*a3p);
    const float bw1 = fabsf(*b1p), bw2 = fabsf(*b2p), bw3 = fabsf(*b3p);
    const float CA = 0.1152f;                 // 0.5*DT/DX^2
    const float CB = 0.2304f;                 // DT/DY^2
    const float TP = 6.283185307179586f;
    const float INV47 = 1.0f / 47.0f;

    const int R0 = 1 + TH * ty;   // padded base row
    const int C0 = 1 + TW * tx;   // padded base col

    float A[TH];
#pragma unroll
    for (int r = 0; r < TH; r++) {
        float t = (float)(TH * ty + r) * INV47;
        A[r] = CA * (aw1 + aw2 * sinf(TP * t) + aw3 * cosf(TP * t));
    }
    float Bv[TW];
#pragma unroll
    for (int c = 0; c < TW; c++) {
        float t = (float)(TW * tx + c) * INV47;
        Bv[c] = CB * (bw1 + bw2 * cosf(TP * t) + bw3 * sinf(TP * t));
    }
    const float B0 = Bv[0], B1 = Bv[1], B2 = Bv[2];

    // time-invariant per-cell center coefficient: cc = 1 - 2A[r] - 2B[c]
    float cc[TH][TW];
#pragma unroll
    for (int r = 0; r < TH; r++)
#pragma unroll
        for (int c = 0; c < TW; c++)
            cc[r][c] = 1.0f - 2.0f * (A[r] + Bv[c]);

    __syncthreads();   // halo + interior visible

    // ---- own tile into registers ----
    float u[TH][TW];
#pragma unroll
    for (int r = 0; r < TH; r++)
#pragma unroll
        for (int c = 0; c < TW; c++)
            u[r][c] = buf0[(R0 + r) * SS + C0 + c];

    // ---- 100 steps: 49 double-steps + peeled final pair (last skips stores) ----
    for (int s = 0; s < NSTEPS - 2; s += 2) {
        step_tile<true>(buf0, buf1, u, A, B0, B1, B2, cc, R0, C0);
        step_tile<true>(buf1, buf0, u, A, B0, B1, B2, cc, R0, C0);
    }
    step_tile<true >(buf0, buf1, u, A, B0, B1, B2, cc, R0, C0);
    step_tile<false>(buf1, buf0, u, A, B0, B1, B2, cc, R0, C0);

    // ---- writeback straight from registers ----
#pragma unroll
    for (int r = 0; r < TH; r++)
#pragma unroll
        for (int c = 0; c < TW; c++)
            gout[(TH * ty + r) * NG + (TW * tx + c)] = u[r][c];
}

extern "C" void kernel_launch(void* const* d_in, const int* in_sizes, int n_in,
                              void* d_out, int out_size)
{
    const float* u0 = (const float*)d_in[0];
    const float* a1 = (const float*)d_in[1];
    const float* a2 = (const float*)d_in[2];
    const float* a3 = (const float*)d_in[3];
    const float* b1 = (const float*)d_in[4];
    const float* b2 = (const float*)d_in[5];
    const float* b3 = (const float*)d_in[6];
    float* out = (float*)d_out;

    int nb = in_sizes[0] / (NG * NG);   // 8192
    pde_stencil_kernel<<<nb, 64>>>(u0, a1, a2, a3, b1, b2, b3, out);
}

// round 12
// speedup vs baseline: 1.2070x; 1.0272x over previous
#include <cuda_runtime.h>
#include <math.h>

// PDELayer: 8192 x (48x48) grids, 100 explicit diffusion steps.
// BATCH-PACKED f32x2: one CTA processes TWO grids; every SMEM cell is a float2
// holding (grid0, grid1). All stencil math is fma.rn.f32x2 / add.rn.f32x2 with
// ZERO pack/unpack in the time loop (neighbors of a pack are packs).
// 64 threads (16x4), each owns a 3-wide x 12-tall pack tile in registers.
// Double-buffered SMEM; only tile PERIMETER packs exchanged (LDS.64/STS.64,
// conflict-free: 3*tx mod 16 bijection, 64-bit accesses resolve per half-warp).
// Reflect halo is time-invariant (reference pads once, updates interior only).

#define NG     48
#define PR     50      // padded rows
#define SS     52      // padded row stride (in packs)
#define NSTEPS 100
#define TW     3
#define TH     12

typedef unsigned long long ull;

__device__ __forceinline__ ull f2fma(ull a, ull b, ull c) {
    ull d; asm("fma.rn.f32x2 %0,%1,%2,%3;" : "=l"(d) : "l"(a), "l"(b), "l"(c)); return d;
}
__device__ __forceinline__ ull f2add(ull a, ull b) {
    ull d; asm("add.rn.f32x2 %0,%1,%2;" : "=l"(d) : "l"(a), "l"(b)); return d;
}
__device__ __forceinline__ ull pk(float lo, float hi) {
    ull v; asm("mov.b64 %0,{%1,%2};" : "=l"(v) : "f"(lo), "f"(hi)); return v;
}
__device__ __forceinline__ void unpk(ull v, float& lo, float& hi) {
    asm("mov.b64 {%0,%1},%2;" : "=f"(lo), "=f"(hi) : "l"(v));
}

template <bool STORE>
__device__ __forceinline__ void step_tile(
    const ull* __restrict__ cur, ull* __restrict__ nxt,
    ull u[TH][TW], const ull A2[TH], const ull B20, const ull B21, const ull B22,
    const ull m2, int R0, int C0)
{
    ull top0 = cur[(R0 - 1) * SS + C0 + 0];
    ull top1 = cur[(R0 - 1) * SS + C0 + 1];
    ull top2 = cur[(R0 - 1) * SS + C0 + 2];
    ull bot0 = cur[(R0 + TH) * SS + C0 + 0];
    ull bot1 = cur[(R0 + TH) * SS + C0 + 1];
    ull bot2 = cur[(R0 + TH) * SS + C0 + 2];

    ull pv0 = 0, pv1 = 0, pv2 = 0;   // old u[r-1]
#pragma unroll
    for (int r = 0; r < TH; r++) {
        ull lf = cur[(R0 + r) * SS + C0 - 1];
        ull rt = cur[(R0 + r) * SS + C0 + TW];

        ull c0 = u[r][0], c1 = u[r][1], c2 = u[r][2];

        ull up0 = (r == 0) ? top0 : pv0;
        ull up1 = (r == 0) ? top1 : pv1;
        ull up2 = (r == 0) ? top2 : pv2;
        ull dn0 = (r == TH - 1) ? bot0 : u[r + 1][0];
        ull dn1 = (r == TH - 1) ? bot1 : u[r + 1][1];
        ull dn2 = (r == TH - 1) ? bot2 : u[r + 1][2];

        // n = u + A[r]*(up+dn-2u) + B[c]*(lf+rt-2u)   (6 f32x2 ops per pack = 3/cell)
        ull sx0 = f2fma(m2, c0, f2add(up0, dn0));
        ull n0  = f2fma(A2[r], sx0, c0);
        ull sy0 = f2fma(m2, c0, f2add(lf, c1));
        n0      = f2fma(B20, sy0, n0);

        ull sx1 = f2fma(m2, c1, f2add(up1, dn1));
        ull n1  = f2fma(A2[r], sx1, c1);
        ull sy1 = f2fma(m2, c1, f2add(c0, c2));
        n1      = f2fma(B21, sy1, n1);

        ull sx2 = f2fma(m2, c2, f2add(up2, dn2));
        ull n2  = f2fma(A2[r], sx2, c2);
        ull sy2 = f2fma(m2, c2, f2add(c1, rt));
        n2      = f2fma(B22, sy2, n2);

        if (STORE) {
            ull* nrow = &nxt[(R0 + r) * SS + C0];
            if (r == 0 || r == TH - 1) {
                nrow[0] = n0; nrow[1] = n1; nrow[2] = n2;
            } else {
                nrow[0] = n0; nrow[2] = n2;
            }
        }

        pv0 = c0; pv1 = c1; pv2 = c2;
        u[r][0] = n0; u[r][1] = n1; u[r][2] = n2;
    }
    if (STORE) __syncthreads();
}

__global__ __launch_bounds__(64, 5)
void pde_stencil_kernel(const float* __restrict__ u0,
                        const float* __restrict__ a1p, const float* __restrict__ a2p,
                        const float* __restrict__ a3p, const float* __restrict__ b1p,
                        const float* __restrict__ b2p, const float* __restrict__ b3p,
                        float* __restrict__ out)
{
    __shared__ __align__(16) ull buf0[PR * SS];
    __shared__ __align__(16) ull buf1[PR * SS];

    const int b   = blockIdx.x;          // pair index: grids 2b, 2b+1
    const int tid = threadIdx.x;
    const int tx  = tid & 15;
    const int ty  = tid >> 4;

    const float* g0 = u0  + (size_t)(2 * b)     * (NG * NG);
    const float* g1 = u0  + (size_t)(2 * b + 1) * (NG * NG);
    float*       o0 = out + (size_t)(2 * b)     * (NG * NG);
    float*       o1 = out + (size_t)(2 * b + 1) * (NG * NG);

    // ---- load interior of BOTH grids into buf0 packs (coalesced gmem) ----
#pragma unroll
    for (int k = 0; k < 36; k++) {
        int c = tid + 64 * k;               // 0..2303
        int i = c / NG, j = c % NG;
        buf0[(i + 1) * SS + (j + 1)] = pk(g0[c], g1[c]);
    }
    __syncthreads();

    // ---- reflect halo (time-invariant) into BOTH buffers ----
    for (int h = tid; h < 196; h += 64) {
        int ii, jj;
        if      (h < 50)  { ii = 0;         jj = h;        }
        else if (h < 100) { ii = 49;        jj = h - 50;   }
        else if (h < 148) { ii = h - 99;    jj = 0;        }   // 1..48
        else              { ii = h - 147;   jj = 49;       }   // 1..48
        int si = (ii == 0) ? 2 : (ii == 49) ? 47 : ii;
        int sj = (jj == 0) ? 2 : (jj == 49) ? 47 : jj;
        ull v = buf0[si * SS + sj];
        buf0[ii * SS + jj] = v;
        buf1[ii * SS + jj] = v;
    }

    // ---- coefficients (batch-invariant; packed as broadcast pairs) ----
    const float aw1 = fabsf(*a1p), aw2 = fabsf(*a2p), aw3 = fabsf(*a3p);
    const float bw1 = fabsf(*b1p), bw2 = fabsf(*b2p), bw3 = fabsf(*b3p);
    const float CA = 0.1152f;                 // 0.5*DT/DX^2
    const float CB = 0.2304f;                 // DT/DY^2
    const float TP = 6.283185307179586f;
    const float INV47 = 1.0f / 47.0f;

    const int R0 = 1 + TH * ty;
    const int C0 = 1 + TW * tx;

    ull A2[TH];
#pragma unroll
    for (int r = 0; r < TH; r++) {
        float t = (float)(TH * ty + r) * INV47;
        float a = CA * (aw1 + aw2 * sinf(TP * t) + aw3 * cosf(TP * t));
        A2[r] = pk(a, a);
    }
    ull B2[TW];
#pragma unroll
    for (int c = 0; c < TW; c++) {
        float t = (float)(TW * tx + c) * INV47;
        float v = CB * (bw1 + bw2 * cosf(TP * t) + bw3 * sinf(TP * t));
        B2[c] = pk(v, v);
    }
    const ull B20 = B2[0], B21 = B2[1], B22 = B2[2];
    const ull m2 = pk(-2.0f, -2.0f);

    __syncthreads();   // interior + halo visible

    // ---- own pack tile into registers ----
    ull u[TH][TW];
#pragma unroll
    for (int r = 0; r < TH; r++)
#pragma unroll
        for (int c = 0; c < TW; c++)
            u[r][c] = buf0[(R0 + r) * SS + C0 + c];

    // ---- 100 steps: double-steps, final step skips stores+barrier ----
    for (int s = 0; s < NSTEPS - 2; s += 2) {
        step_tile<true>(buf0, buf1, u, A2, B20, B21, B22, m2, R0, C0);
        step_tile<true>(buf1, buf0, u, A2, B20, B21, B22, m2, R0, C0);
    }
    step_tile<true >(buf0, buf1, u, A2, B20, B21, B22, m2, R0, C0);
    step_tile<false>(buf1, buf0, u, A2, B20, B21, B22, m2, R0, C0);

    // ---- writeback both grids straight from registers ----
#pragma unroll
    for (int r = 0; r < TH; r++)
#pragma unroll
        for (int c = 0; c < TW; c++) {
            float lo, hi;
            unpk(u[r][c], lo, hi);
            int gi = (TH * ty + r) * NG + (TW * tx + c);
            o0[gi] = lo;
            o1[gi] = hi;
        }
}

extern "C" void kernel_launch(void* const* d_in, const int* in_sizes, int n_in,
                              void* d_out, int out_size)
{
    const float* u0 = (const float*)d_in[0];
    const float* a1 = (const float*)d_in[1];
    const float* a2 = (const float*)d_in[2];
    const float* a3 = (const float*)d_in[3];
    const float* b1 = (const float*)d_in[4];
    const float* b2 = (const float*)d_in[5];
    const float* b3 = (const float*)d_in[6];
    float* out = (float*)d_out;

    // allow SMEM (not default carveout) to set occupancy: 41.6 KB/CTA -> 5 CTAs/SM
    static int carveout_set = 0;
    if (!carveout_set) {
        cudaFuncSetAttribute(pde_stencil_kernel,
                             cudaFuncAttributePreferredSharedMemoryCarveout, 100);
        carveout_set = 1;
    }

    int nb = in_sizes[0] / (2 * NG * NG);   // 4096 grid pairs
    pde_stencil_kernel<<<nb, 64>>>(u0, a1, a2, a3, b1, b2, b3, out);
}

// round 13
// speedup vs baseline: 1.2237x; 1.0138x over previous
#include <cuda_runtime.h>
#include <math.h>

// PDELayer: 8192 x (48x48) grids, 100 explicit diffusion steps.
// BATCH-PACKED f32x2: one CTA processes TWO grids; every SMEM cell is a float2
// holding (grid0, grid1). All stencil math is fma.rn.f32x2 / add.rn.f32x2 with
// ZERO pack/unpack in the time loop (neighbors of a pack are packs).
// 128 threads (16x8), each owns a 3-wide x 6-tall pack tile in registers
// (R12 lesson: 64 threads x 3x12 tiles left only 10 warps/SM, issue 46%).
// Double-buffered SMEM; only tile PERIMETER packs exchanged (LDS.64/STS.64,
// conflict-free: byte offset 24*tx -> bank pairs {6tx,6tx+1} mod 32 distinct).
// Reflect halo is time-invariant (reference pads once, updates interior only).

#define NG     48
#define PR     50      // padded rows
#define SS     52      // padded row stride (in packs)
#define NSTEPS 100
#define TW     3
#define TH     6
#define NTHR   128

typedef unsigned long long ull;

__device__ __forceinline__ ull f2fma(ull a, ull b, ull c) {
    ull d; asm("fma.rn.f32x2 %0,%1,%2,%3;" : "=l"(d) : "l"(a), "l"(b), "l"(c)); return d;
}
__device__ __forceinline__ ull f2add(ull a, ull b) {
    ull d; asm("add.rn.f32x2 %0,%1,%2;" : "=l"(d) : "l"(a), "l"(b)); return d;
}
__device__ __forceinline__ ull pk(float lo, float hi) {
    ull v; asm("mov.b64 %0,{%1,%2};" : "=l"(v) : "f"(lo), "f"(hi)); return v;
}
__device__ __forceinline__ void unpk(ull v, float& lo, float& hi) {
    asm("mov.b64 {%0,%1},%2;" : "=f"(lo), "=f"(hi) : "l"(v));
}

template <bool STORE>
__device__ __forceinline__ void step_tile(
    const ull* __restrict__ cur, ull* __restrict__ nxt,
    ull u[TH][TW], const ull A2[TH], const ull B20, const ull B21, const ull B22,
    const ull m2, int R0, int C0)
{
    ull top0 = cur[(R0 - 1) * SS + C0 + 0];
    ull top1 = cur[(R0 - 1) * SS + C0 + 1];
    ull top2 = cur[(R0 - 1) * SS + C0 + 2];
    ull bot0 = cur[(R0 + TH) * SS + C0 + 0];
    ull bot1 = cur[(R0 + TH) * SS + C0 + 1];
    ull bot2 = cur[(R0 + TH) * SS + C0 + 2];

    ull pv0 = 0, pv1 = 0, pv2 = 0;   // old u[r-1]
#pragma unroll
    for (int r = 0; r < TH; r++) {
        ull lf = cur[(R0 + r) * SS + C0 - 1];
        ull rt = cur[(R0 + r) * SS + C0 + TW];

        ull c0 = u[r][0], c1 = u[r][1], c2 = u[r][2];

        ull up0 = (r == 0) ? top0 : pv0;
        ull up1 = (r == 0) ? top1 : pv1;
        ull up2 = (r == 0) ? top2 : pv2;
        ull dn0 = (r == TH - 1) ? bot0 : u[r + 1][0];
        ull dn1 = (r == TH - 1) ? bot1 : u[r + 1][1];
        ull dn2 = (r == TH - 1) ? bot2 : u[r + 1][2];

        // n = u + A[r]*(up+dn-2u) + B[c]*(lf+rt-2u)   (6 f32x2 ops per pack)
        ull sx0 = f2fma(m2, c0, f2add(up0, dn0));
        ull n0  = f2fma(A2[r], sx0, c0);
        ull sy0 = f2fma(m2, c0, f2add(lf, c1));
        n0      = f2fma(B20, sy0, n0);

        ull sx1 = f2fma(m2, c1, f2add(up1, dn1));
        ull n1  = f2fma(A2[r], sx1, c1);
        ull sy1 = f2fma(m2, c1, f2add(c0, c2));
        n1      = f2fma(B21, sy1, n1);

        ull sx2 = f2fma(m2, c2, f2add(up2, dn2));
        ull n2  = f2fma(A2[r], sx2, c2);
        ull sy2 = f2fma(m2, c2, f2add(c1, rt));
        n2      = f2fma(B22, sy2, n2);

        if (STORE) {
            ull* nrow = &nxt[(R0 + r) * SS + C0];
            if (r == 0 || r == TH - 1) {
                nrow[0] = n0; nrow[1] = n1; nrow[2] = n2;
            } else {
                nrow[0] = n0; nrow[2] = n2;
            }
        }

        pv0 = c0; pv1 = c1; pv2 = c2;
        u[r][0] = n0; u[r][1] = n1; u[r][2] = n2;
    }
    if (STORE) __syncthreads();
}

__global__ __launch_bounds__(NTHR, 5)
void pde_stencil_kernel(const float* __restrict__ u0,
                        const float* __restrict__ a1p, const float* __restrict__ a2p,
                        const float* __restrict__ a3p, const float* __restrict__ b1p,
                        const float* __restrict__ b2p, const float* __restrict__ b3p,
                        float* __restrict__ out)
{
    __shared__ __align__(16) ull buf0[PR * SS];
    __shared__ __align__(16) ull buf1[PR * SS];

    const int b   = blockIdx.x;          // pair index: grids 2b, 2b+1
    const int tid = threadIdx.x;
    const int tx  = tid & 15;            // 0..15
    const int ty  = tid >> 4;            // 0..7

    const float* g0 = u0  + (size_t)(2 * b)     * (NG * NG);
    const float* g1 = u0  + (size_t)(2 * b + 1) * (NG * NG);
    float*       o0 = out + (size_t)(2 * b)     * (NG * NG);
    float*       o1 = out + (size_t)(2 * b + 1) * (NG * NG);

    // ---- load interior of BOTH grids into buf0 packs (coalesced gmem) ----
#pragma unroll
    for (int k = 0; k < 18; k++) {
        int c = tid + NTHR * k;             // 0..2303
        int i = c / NG, j = c % NG;
        buf0[(i + 1) * SS + (j + 1)] = pk(g0[c], g1[c]);
    }
    __syncthreads();

    // ---- reflect halo (time-invariant) into BOTH buffers ----
    for (int h = tid; h < 196; h += NTHR) {
        int ii, jj;
        if      (h < 50)  { ii = 0;         jj = h;        }
        else if (h < 100) { ii = 49;        jj = h - 50;   }
        else if (h < 148) { ii = h - 99;    jj = 0;        }   // 1..48
        else              { ii = h - 147;   jj = 49;       }   // 1..48
        int si = (ii == 0) ? 2 : (ii == 49) ? 47 : ii;
        int sj = (jj == 0) ? 2 : (jj == 49) ? 47 : jj;
        ull v = buf0[si * SS + sj];
        buf0[ii * SS + jj] = v;
        buf1[ii * SS + jj] = v;
    }

    // ---- coefficients (batch-invariant; packed as broadcast pairs) ----
    const float aw1 = fabsf(*a1p), aw2 = fabsf(*a2p), aw3 = fabsf(*a3p);
    const float bw1 = fabsf(*b1p), bw2 = fabsf(*b2p), bw3 = fabsf(*b3p);
    const float CA = 0.1152f;                 // 0.5*DT/DX^2
    const float CB = 0.2304f;                 // DT/DY^2
    const float TP = 6.283185307179586f;
    const float INV47 = 1.0f / 47.0f;

    const int R0 = 1 + TH * ty;
    const int C0 = 1 + TW * tx;

    ull A2[TH];
#pragma unroll
    for (int r = 0; r < TH; r++) {
        float t = (float)(TH * ty + r) * INV47;
        float a = CA * (aw1 + aw2 * sinf(TP * t) + aw3 * cosf(TP * t));
        A2[r] = pk(a, a);
    }
    ull B2[TW];
#pragma unroll
    for (int c = 0; c < TW; c++) {
        float t = (float)(TW * tx + c) * INV47;
        float v = CB * (bw1 + bw2 * cosf(TP * t) + bw3 * sinf(TP * t));
        B2[c] = pk(v, v);
    }
    const ull B20 = B2[0], B21 = B2[1], B22 = B2[2];
    const ull m2 = pk(-2.0f, -2.0f);

    __syncthreads();   // interior + halo visible

    // ---- own pack tile into registers ----
    ull u[TH][TW];
#pragma unroll
    for (int r = 0; r < TH; r++)
#pragma unroll
        for (int c = 0; c < TW; c++)
            u[r][c] = buf0[(R0 + r) * SS + C0 + c];

    // ---- 100 steps: double-steps, final step skips stores+barrier ----
    for (int s = 0; s < NSTEPS - 2; s += 2) {
        step_tile<true>(buf0, buf1, u, A2, B20, B21, B22, m2, R0, C0);
        step_tile<true>(buf1, buf0, u, A2, B20, B21, B22, m2, R0, C0);
    }
    step_tile<true >(buf0, buf1, u, A2, B20, B21, B22, m2, R0, C0);
    step_tile<false>(buf1, buf0, u, A2, B20, B21, B22, m2, R0, C0);

    // ---- writeback both grids straight from registers ----
#pragma unroll
    for (int r = 0; r < TH; r++)
#pragma unroll
        for (int c = 0; c < TW; c++) {
            float lo, hi;
            unpk(u[r][c], lo, hi);
            int gi = (TH * ty + r) * NG + (TW * tx + c);
            o0[gi] = lo;
            o1[gi] = hi;
        }
}

extern "C" void kernel_launch(void* const* d_in, const int* in_sizes, int n_in,
                              void* d_out, int out_size)
{
    const float* u0 = (const float*)d_in[0];
    const float* a1 = (const float*)d_in[1];
    const float* a2 = (const float*)d_in[2];
    const float* a3 = (const float*)d_in[3];
    const float* b1 = (const float*)d_in[4];
    const float* b2 = (const float*)d_in[5];
    const float* b3 = (const float*)d_in[6];
    float* out = (float*)d_out;

    // allow SMEM (not default carveout) to set occupancy: 41.6 KB/CTA -> 5 CTAs/SM
    static int carveout_set = 0;
    if (!carveout_set) {
        cudaFuncSetAttribute(pde_stencil_kernel,
                             cudaFuncAttributePreferredSharedMemoryCarveout, 100);
        carveout_set = 1;
    }

    int nb = in_sizes[0] / (2 * NG * NG);   // 4096 grid pairs
    pde_stencil_kernel<<<nb, NTHR>>>(u0, a1, a2, a3, b1, b2, b3, out);
}